// round 1
// baseline (speedup 1.0000x reference)
#include <cuda_runtime.h>
#include <cuda_bf16.h>
#include <math.h>

// ---------------- problem constants ----------------
#define BSZ 32
#define TT 197           // tokens
#define TD 768           // token dim
#define NH 12            // heads
#define HD 64            // head dim
#define NB 12            // blocks
#define MD 3072          // mlp dim
#define OD 1000          // out dim
#define NPATCH 196
#define M_TOK (BSZ*TT)   // 6304
#define M_PATCH (BSZ*NPATCH) // 6272
#define ATT_SCALE 0.125f
#define LN_EPS 1e-5f

// ---------------- scratch (device globals, no allocation) ----------------
__device__ float g_x[M_TOK*TD];
__device__ float g_h[M_TOK*TD];
__device__ float g_q[M_TOK*TD];
__device__ float g_k[M_TOK*TD];
__device__ float g_v[M_TOK*TD];
__device__ float g_mlp[(size_t)M_TOK*MD];
__device__ float g_patches[(size_t)M_PATCH*TD];

// ---------------- small reductions ----------------
__device__ __forceinline__ float warpSum(float v){
    #pragma unroll
    for (int o=16;o;o>>=1) v += __shfl_xor_sync(0xffffffffu, v, o);
    return v;
}
__device__ __forceinline__ float warpMax(float v){
    #pragma unroll
    for (int o=16;o;o>>=1) v = fmaxf(v, __shfl_xor_sync(0xffffffffu, v, o));
    return v;
}
__device__ __forceinline__ float blockSum256(float v){
    __shared__ float red[8];
    __shared__ float total;
    int lane = threadIdx.x & 31, w = threadIdx.x >> 5;
    v = warpSum(v);
    if (lane == 0) red[w] = v;
    __syncthreads();
    if (threadIdx.x == 0){ float s=0.f; for(int i=0;i<8;i++) s += red[i]; total = s; }
    __syncthreads();
    float r = total;
    __syncthreads();
    return r;
}
__device__ __forceinline__ float blockMax256(float v){
    __shared__ float red[8];
    __shared__ float total;
    int lane = threadIdx.x & 31, w = threadIdx.x >> 5;
    v = warpMax(v);
    if (lane == 0) red[w] = v;
    __syncthreads();
    if (threadIdx.x == 0){ float s=-1e30f; for(int i=0;i<8;i++) s = fmaxf(s, red[i]); total = s; }
    __syncthreads();
    float r = total;
    __syncthreads();
    return r;
}

// ---------------- patchify ----------------
__global__ void patchify_kernel(const float* __restrict__ img){
    int idx = blockIdx.x*blockDim.x + threadIdx.x;
    if (idx >= M_PATCH*TD) return;
    int d = idx % TD;
    int mp = idx / TD;
    int b = mp / NPATCH;
    int p = mp % NPATCH;
    int py = p / 14, px = p % 14;
    int c = d >> 8;          // /256
    int r = d & 255;
    int iy = r >> 4, ix = r & 15;
    g_patches[idx] = img[ (((size_t)(b*3 + c)*224) + py*16 + iy)*224 + px*16 + ix ];
}

// ---------------- cls + pos-emb assembly ----------------
__global__ void assemble_kernel(const float* __restrict__ vcls, const float* __restrict__ tokens){
    int idx = blockIdx.x*blockDim.x + threadIdx.x;
    if (idx >= M_TOK*TD) return;
    int d = idx % TD;
    int m = idx / TD;
    int b = m / TT;
    int s = m % TT;
    float val = (s == 0) ? vcls[d] : tokens[(size_t)(b*NPATCH + s - 1)*TD + d];
    float je = (float)(d & ~1);
    // 1 / 10000^(je/197) = exp2(-je * log2(10000)/197)
    float ang = (float)s * exp2f(-je * (13.287712379549449f / 197.0f));
    val += (d & 1) ? cosf(ang) : sinf(ang);
    g_x[idx] = val;
}

// ---------------- layernorm (row per block) ----------------
__global__ void layernorm_kernel(const float* __restrict__ x, float* __restrict__ out,
                                 const float* __restrict__ g, const float* __restrict__ b){
    __shared__ float sdata[TD];
    int row = blockIdx.x;
    const float* xr = x + (size_t)row*TD;
    float local = 0.f;
    for (int i = threadIdx.x; i < TD; i += 256){ float v = xr[i]; sdata[i] = v; local += v; }
    float mean = blockSum256(local) * (1.0f/TD);
    float lv = 0.f;
    for (int i = threadIdx.x; i < TD; i += 256){ float t = sdata[i]-mean; lv += t*t; }
    float var = blockSum256(lv) * (1.0f/TD);
    float rstd = rsqrtf(var + LN_EPS);
    float* orow = out + (size_t)row*TD;
    for (int i = threadIdx.x; i < TD; i += 256)
        orow[i] = (sdata[i]-mean)*rstd*g[i] + b[i];
}

// ---------------- per-head QKV projection ----------------
// grid (ceil(M_TOK/64), NH), 256 threads
__global__ void qkv_kernel(const float* __restrict__ Wq, const float* __restrict__ bq,
                           const float* __restrict__ Wk, const float* __restrict__ bk,
                           const float* __restrict__ Wv, const float* __restrict__ bv){
    __shared__ float Hs[64][65];
    __shared__ float Ws[64][64];
    int h = blockIdx.y;
    int m0 = blockIdx.x * 64;
    int tid = threadIdx.x;

    for (int i = tid; i < 64*64; i += 256){
        int r = i >> 6, cc = i & 63;
        int row = m0 + r;
        Hs[r][cc] = (row < M_TOK) ? g_h[(size_t)row*TD + h*64 + cc] : 0.f;
    }
    const float* Wp[3] = {Wq, Wk, Wv};
    const float* bp[3] = {bq, bk, bv};
    float* op[3] = {g_q, g_k, g_v};
    int ty = tid >> 4, tx = tid & 15;

    for (int m = 0; m < 3; m++){
        __syncthreads();
        const float* W = Wp[m] + (size_t)h*64*64;
        for (int i = tid; i < 64*64; i += 256) Ws[i>>6][i&63] = W[i];
        __syncthreads();
        float acc[4][4];
        #pragma unroll
        for (int i=0;i<4;i++)
            #pragma unroll
            for (int j=0;j<4;j++) acc[i][j]=0.f;
        #pragma unroll 8
        for (int kd = 0; kd < 64; kd++){
            float a[4], bb[4];
            #pragma unroll
            for (int i=0;i<4;i++) a[i] = Hs[ty*4+i][kd];
            #pragma unroll
            for (int j=0;j<4;j++) bb[j] = Ws[kd][tx*4+j];
            #pragma unroll
            for (int i=0;i<4;i++)
                #pragma unroll
                for (int j=0;j<4;j++) acc[i][j] = fmaf(a[i], bb[j], acc[i][j]);
        }
        #pragma unroll
        for (int i=0;i<4;i++){
            int row = m0 + ty*4 + i;
            if (row >= M_TOK) continue;
            #pragma unroll
            for (int j=0;j<4;j++){
                int e = tx*4 + j;
                op[m][(size_t)row*TD + h*64 + e] = acc[i][j] + bp[m][h*64 + e];
            }
        }
    }
}

// ---------------- fused attention (per (b,h)), residual add into x ----------------
// grid (NH, BSZ), 256 threads, dynamic smem
__global__ void attn_kernel(){
    extern __shared__ float sm[];
    float* Kt = sm;                 // [64][200]
    float* Vs = Kt + 64*200;        // [197][64]
    float* q8 = Vs + TT*64;         // [8][64]
    float* p8 = q8 + 8*64;          // [8][224]

    int h = blockIdx.x, b = blockIdx.y;
    int tid = threadIdx.x;
    size_t base = ((size_t)b*TT)*TD + h*64;

    for (int i = tid; i < TT*64; i += 256){
        int k = i >> 6, d = i & 63;
        float kv = g_k[base + (size_t)k*TD + d];
        Kt[d*200 + k] = kv;
        Vs[i] = g_v[base + (size_t)k*TD + d];
    }
    __syncthreads();

    int w = tid >> 5, lane = tid & 31;
    float* qr = q8 + w*64;
    float* pr = p8 + w*224;

    for (int s = w; s < TT; s += 8){
        qr[lane]      = g_q[base + (size_t)s*TD + lane];
        qr[lane + 32] = g_q[base + (size_t)s*TD + lane + 32];
        __syncwarp();
        float lmax = -1e30f;
        for (int k = lane; k < TT; k += 32){
            float dot = 0.f;
            #pragma unroll
            for (int d = 0; d < 64; d++) dot = fmaf(qr[d], Kt[d*200 + k], dot);
            dot *= ATT_SCALE;
            pr[k] = dot;
            lmax = fmaxf(lmax, dot);
        }
        lmax = warpMax(lmax);
        float lsum = 0.f;
        for (int k = lane; k < TT; k += 32){
            float e = expf(pr[k] - lmax);
            pr[k] = e;
            lsum += e;
        }
        lsum = warpSum(lsum);
        float inv = 1.0f / lsum;
        __syncwarp();
        float acc0 = 0.f, acc1 = 0.f;
        for (int k = 0; k < TT; k++){
            float p = pr[k];
            acc0 = fmaf(p, Vs[k*64 + lane],      acc0);
            acc1 = fmaf(p, Vs[k*64 + lane + 32], acc1);
        }
        size_t xi = base + (size_t)s*TD;
        g_x[xi + lane]      += acc0 * inv;
        g_x[xi + lane + 32] += acc1 * inv;
        __syncwarp();
    }
}

// ---------------- generic SGEMM: C (epi) A[M,K] @ B[K,N] + bias ----------------
// epi: 0 = store, 1 = store gelu, 2 = C += (residual)
// requires: N % 128 == 0, K % 8 == 0
__global__ void sgemm_kernel(const float* __restrict__ A, const float* __restrict__ Bm,
                             const float* __restrict__ bias, float* __restrict__ C,
                             int M, int N, int K, int epi){
    __shared__ float As[8][128];
    __shared__ float Bs[8][128];
    int tid = threadIdx.x;
    int row0 = blockIdx.y * 128;
    int col0 = blockIdx.x * 128;
    int tx = tid & 15, ty = tid >> 4;

    float acc[8][8];
    #pragma unroll
    for (int i=0;i<8;i++)
        #pragma unroll
        for (int j=0;j<8;j++) acc[i][j]=0.f;

    int arow = tid >> 1;
    int acol = (tid & 1) * 4;
    int brow = tid >> 5;
    int bcol = (tid & 31) * 4;

    for (int kk = 0; kk < K; kk += 8){
        float4 av;
        int grow = row0 + arow;
        if (grow < M) av = *(const float4*)&A[(size_t)grow*K + kk + acol];
        else av = make_float4(0.f,0.f,0.f,0.f);
        As[acol+0][arow] = av.x;
        As[acol+1][arow] = av.y;
        As[acol+2][arow] = av.z;
        As[acol+3][arow] = av.w;
        *(float4*)&Bs[brow][bcol] = *(const float4*)&Bm[(size_t)(kk+brow)*N + col0 + bcol];
        __syncthreads();
        #pragma unroll
        for (int k = 0; k < 8; k++){
            float a[8], bb[8];
            *(float4*)(a)   = *(float4*)&As[k][ty*8];
            *(float4*)(a+4) = *(float4*)&As[k][ty*8+4];
            *(float4*)(bb)   = *(float4*)&Bs[k][tx*8];
            *(float4*)(bb+4) = *(float4*)&Bs[k][tx*8+4];
            #pragma unroll
            for (int i=0;i<8;i++)
                #pragma unroll
                for (int j=0;j<8;j++) acc[i][j] = fmaf(a[i], bb[j], acc[i][j]);
        }
        __syncthreads();
    }

    #pragma unroll
    for (int i=0;i<8;i++){
        int r = row0 + ty*8 + i;
        if (r >= M) continue;
        #pragma unroll
        for (int j=0;j<8;j++){
            int c = col0 + tx*8 + j;
            float v = acc[i][j] + bias[c];
            size_t idx = (size_t)r*N + c;
            if (epi == 1){
                v = 0.5f * v * (1.0f + erff(v * 0.70710678118654752f));
                C[idx] = v;
            } else if (epi == 2){
                C[idx] += v;
            } else {
                C[idx] = v;
            }
        }
    }
}

// ---------------- classifier head + softmax ----------------
__global__ void classifier_kernel(const float* __restrict__ Wout, const float* __restrict__ bout,
                                  float* __restrict__ out){
    __shared__ float xs[TD];
    __shared__ float lg[OD];
    int b = blockIdx.x;
    int tid = threadIdx.x;
    for (int i = tid; i < TD; i += 256) xs[i] = g_x[((size_t)b*TT)*TD + i];
    __syncthreads();
    for (int n = tid; n < OD; n += 256){
        float s = bout[n];
        for (int d = 0; d < TD; d++) s = fmaf(xs[d], Wout[(size_t)d*OD + n], s);
        lg[n] = s;
    }
    __syncthreads();
    float lm = -1e30f;
    for (int n = tid; n < OD; n += 256) lm = fmaxf(lm, lg[n]);
    lm = blockMax256(lm);
    float ls = 0.f;
    for (int n = tid; n < OD; n += 256){
        float e = expf(lg[n] - lm);
        lg[n] = e;
        ls += e;
    }
    ls = blockSum256(ls);
    float inv = 1.0f / ls;
    for (int n = tid; n < OD; n += 256) out[(size_t)b*OD + n] = lg[n] * inv;
}

// ---------------- host orchestration ----------------
extern "C" void kernel_launch(void* const* d_in, const int* in_sizes, int n_in,
                              void* d_out, int out_size){
    const float* images  = (const float*)d_in[0];
    const float* W_embed = (const float*)d_in[1];
    const float* b_embed = (const float*)d_in[2];
    const float* v_class = (const float*)d_in[3];
    const float* ln1_g   = (const float*)d_in[4];
    const float* ln1_b   = (const float*)d_in[5];
    const float* ln2_g   = (const float*)d_in[6];
    const float* ln2_b   = (const float*)d_in[7];
    const float* Wq      = (const float*)d_in[8];
    const float* bq      = (const float*)d_in[9];
    const float* Wk      = (const float*)d_in[10];
    const float* bk      = (const float*)d_in[11];
    const float* Wv      = (const float*)d_in[12];
    const float* bv      = (const float*)d_in[13];
    const float* Wm1     = (const float*)d_in[14];
    const float* bm1     = (const float*)d_in[15];
    const float* Wm2     = (const float*)d_in[16];
    const float* bm2     = (const float*)d_in[17];
    const float* Wout    = (const float*)d_in[18];
    const float* bout    = (const float*)d_in[19];
    float* out = (float*)d_out;

    float *px, *ph, *pmlp, *ppatch;
    cudaGetSymbolAddress((void**)&px, g_x);
    cudaGetSymbolAddress((void**)&ph, g_h);
    cudaGetSymbolAddress((void**)&pmlp, g_mlp);
    cudaGetSymbolAddress((void**)&ppatch, g_patches);

    const int ATT_SMEM = (64*200 + TT*64 + 8*64 + 8*224) * 4; // 110848 bytes
    cudaFuncSetAttribute(attn_kernel, cudaFuncAttributeMaxDynamicSharedMemorySize, ATT_SMEM);

    // patchify + embed
    patchify_kernel<<<(M_PATCH*TD + 255)/256, 256>>>(images);
    {
        dim3 g(TD/128, (M_PATCH + 127)/128);
        sgemm_kernel<<<g, 256>>>(ppatch, W_embed, b_embed, pmlp, M_PATCH, TD, TD, 0);
    }
    assemble_kernel<<<(M_TOK*TD + 255)/256, 256>>>(v_class, pmlp);

    for (int l = 0; l < NB; l++){
        layernorm_kernel<<<M_TOK, 256>>>(px, ph, ln1_g + l*TD, ln1_b + l*TD);
        {
            dim3 g((M_TOK + 63)/64, NH);
            qkv_kernel<<<g, 256>>>(Wq + (size_t)l*NH*64*64, bq + (size_t)l*NH*64,
                                   Wk + (size_t)l*NH*64*64, bk + (size_t)l*NH*64,
                                   Wv + (size_t)l*NH*64*64, bv + (size_t)l*NH*64);
        }
        attn_kernel<<<dim3(NH, BSZ), 256, ATT_SMEM>>>();
        layernorm_kernel<<<M_TOK, 256>>>(px, ph, ln2_g + l*TD, ln2_b + l*TD);
        {
            dim3 g(MD/128, (M_TOK + 127)/128);
            sgemm_kernel<<<g, 256>>>(ph, Wm1 + (size_t)l*TD*MD, bm1 + (size_t)l*MD,
                                     pmlp, M_TOK, MD, TD, 1);
        }
        {
            dim3 g(TD/128, (M_TOK + 127)/128);
            sgemm_kernel<<<g, 256>>>(pmlp, Wm2 + (size_t)l*MD*TD, bm2 + (size_t)l*TD,
                                     px, M_TOK, TD, MD, 2);
        }
    }

    classifier_kernel<<<BSZ, 256>>>(Wout, bout, out);
}

// round 2
// speedup vs baseline: 1.8031x; 1.8031x over previous
#include <cuda_runtime.h>
#include <cuda_bf16.h>
#include <math.h>

// ---------------- problem constants ----------------
#define BSZ 32
#define TT 197           // tokens
#define TD 768           // token dim
#define NH 12            // heads
#define HD 64            // head dim
#define NB 12            // blocks
#define MD 3072          // mlp dim
#define OD 1000          // out dim
#define NPATCH 196
#define M_TOK (BSZ*TT)   // 6304
#define M_PATCH (BSZ*NPATCH) // 6272
#define ATT_SCALE 0.125f
#define LN_EPS 1e-5f

// ---------------- scratch (device globals, no allocation) ----------------
__device__ float g_x[M_TOK*TD];
__device__ float g_h[M_TOK*TD];
__device__ float g_q[M_TOK*TD];
__device__ float g_k[M_TOK*TD];
__device__ float g_v[M_TOK*TD];
__device__ float g_mlp[(size_t)M_TOK*MD];
__device__ float g_patches[(size_t)M_PATCH*TD];

// ---------------- small reductions ----------------
__device__ __forceinline__ float warpSum(float v){
    #pragma unroll
    for (int o=16;o;o>>=1) v += __shfl_xor_sync(0xffffffffu, v, o);
    return v;
}
__device__ __forceinline__ float warpMax(float v){
    #pragma unroll
    for (int o=16;o;o>>=1) v = fmaxf(v, __shfl_xor_sync(0xffffffffu, v, o));
    return v;
}
__device__ __forceinline__ float blockSum256(float v){
    __shared__ float red[8];
    __shared__ float total;
    int lane = threadIdx.x & 31, w = threadIdx.x >> 5;
    v = warpSum(v);
    if (lane == 0) red[w] = v;
    __syncthreads();
    if (threadIdx.x == 0){ float s=0.f; for(int i=0;i<8;i++) s += red[i]; total = s; }
    __syncthreads();
    float r = total;
    __syncthreads();
    return r;
}
__device__ __forceinline__ float blockMax256(float v){
    __shared__ float red[8];
    __shared__ float total;
    int lane = threadIdx.x & 31, w = threadIdx.x >> 5;
    v = warpMax(v);
    if (lane == 0) red[w] = v;
    __syncthreads();
    if (threadIdx.x == 0){ float s=-1e30f; for(int i=0;i<8;i++) s = fmaxf(s, red[i]); total = s; }
    __syncthreads();
    float r = total;
    __syncthreads();
    return r;
}

// ---------------- tf32 helper ----------------
__device__ __forceinline__ unsigned f2tf(float x){
    unsigned u; asm("cvt.rna.tf32.f32 %0, %1;" : "=r"(u) : "f"(x)); return u;
}

// ---------------- patchify ----------------
__global__ void patchify_kernel(const float* __restrict__ img){
    int idx = blockIdx.x*blockDim.x + threadIdx.x;
    if (idx >= M_PATCH*TD) return;
    int d = idx % TD;
    int mp = idx / TD;
    int b = mp / NPATCH;
    int p = mp % NPATCH;
    int py = p / 14, px = p % 14;
    int c = d >> 8;          // /256
    int r = d & 255;
    int iy = r >> 4, ix = r & 15;
    g_patches[idx] = img[ (((size_t)(b*3 + c)*224) + py*16 + iy)*224 + px*16 + ix ];
}

// ---------------- cls + pos-emb assembly ----------------
__global__ void assemble_kernel(const float* __restrict__ vcls, const float* __restrict__ tokens){
    int idx = blockIdx.x*blockDim.x + threadIdx.x;
    if (idx >= M_TOK*TD) return;
    int d = idx % TD;
    int m = idx / TD;
    int b = m / TT;
    int s = m % TT;
    float val = (s == 0) ? vcls[d] : tokens[(size_t)(b*NPATCH + s - 1)*TD + d];
    float je = (float)(d & ~1);
    float ang = (float)s * exp2f(-je * (13.287712379549449f / 197.0f));
    val += (d & 1) ? cosf(ang) : sinf(ang);
    g_x[idx] = val;
}

// ---------------- layernorm (row per block) ----------------
__global__ void layernorm_kernel(const float* __restrict__ x, float* __restrict__ out,
                                 const float* __restrict__ g, const float* __restrict__ b){
    __shared__ float sdata[TD];
    int row = blockIdx.x;
    const float* xr = x + (size_t)row*TD;
    float local = 0.f;
    for (int i = threadIdx.x; i < TD; i += 256){ float v = xr[i]; sdata[i] = v; local += v; }
    float mean = blockSum256(local) * (1.0f/TD);
    float lv = 0.f;
    for (int i = threadIdx.x; i < TD; i += 256){ float t = sdata[i]-mean; lv += t*t; }
    float var = blockSum256(lv) * (1.0f/TD);
    float rstd = rsqrtf(var + LN_EPS);
    float* orow = out + (size_t)row*TD;
    for (int i = threadIdx.x; i < TD; i += 256)
        orow[i] = (sdata[i]-mean)*rstd*g[i] + b[i];
}

// ---------------- per-head QKV projection ----------------
__global__ void qkv_kernel(const float* __restrict__ Wq, const float* __restrict__ bq,
                           const float* __restrict__ Wk, const float* __restrict__ bk,
                           const float* __restrict__ Wv, const float* __restrict__ bv){
    __shared__ float Hs[64][65];
    __shared__ float Ws[64][64];
    int h = blockIdx.y;
    int m0 = blockIdx.x * 64;
    int tid = threadIdx.x;

    for (int i = tid; i < 64*64; i += 256){
        int r = i >> 6, cc = i & 63;
        int row = m0 + r;
        Hs[r][cc] = (row < M_TOK) ? g_h[(size_t)row*TD + h*64 + cc] : 0.f;
    }
    const float* Wp[3] = {Wq, Wk, Wv};
    const float* bp[3] = {bq, bk, bv};
    float* op[3] = {g_q, g_k, g_v};
    int ty = tid >> 4, tx = tid & 15;

    for (int m = 0; m < 3; m++){
        __syncthreads();
        const float* W = Wp[m] + (size_t)h*64*64;
        for (int i = tid; i < 64*64; i += 256) Ws[i>>6][i&63] = W[i];
        __syncthreads();
        float acc[4][4];
        #pragma unroll
        for (int i=0;i<4;i++)
            #pragma unroll
            for (int j=0;j<4;j++) acc[i][j]=0.f;
        #pragma unroll 8
        for (int kd = 0; kd < 64; kd++){
            float a[4], bb[4];
            #pragma unroll
            for (int i=0;i<4;i++) a[i] = Hs[ty*4+i][kd];
            #pragma unroll
            for (int j=0;j<4;j++) bb[j] = Ws[kd][tx*4+j];
            #pragma unroll
            for (int i=0;i<4;i++)
                #pragma unroll
                for (int j=0;j<4;j++) acc[i][j] = fmaf(a[i], bb[j], acc[i][j]);
        }
        #pragma unroll
        for (int i=0;i<4;i++){
            int row = m0 + ty*4 + i;
            if (row >= M_TOK) continue;
            #pragma unroll
            for (int j=0;j<4;j++){
                int e = tx*4 + j;
                op[m][(size_t)row*TD + h*64 + e] = acc[i][j] + bp[m][h*64 + e];
            }
        }
    }
}

// ---------------- fused attention (per (b,h)), residual add into x ----------------
__global__ void attn_kernel(){
    extern __shared__ float sm[];
    float* Kt = sm;                 // [64][200]
    float* Vs = Kt + 64*200;        // [197][64]
    float* q8 = Vs + TT*64;         // [8][64]
    float* p8 = q8 + 8*64;          // [8][224]

    int h = blockIdx.x, b = blockIdx.y;
    int tid = threadIdx.x;
    size_t base = ((size_t)b*TT)*TD + h*64;

    for (int i = tid; i < TT*64; i += 256){
        int k = i >> 6, d = i & 63;
        float kv = g_k[base + (size_t)k*TD + d];
        Kt[d*200 + k] = kv;
        Vs[i] = g_v[base + (size_t)k*TD + d];
    }
    __syncthreads();

    int w = tid >> 5, lane = tid & 31;
    float* qr = q8 + w*64;
    float* pr = p8 + w*224;

    for (int s = w; s < TT; s += 8){
        qr[lane]      = g_q[base + (size_t)s*TD + lane];
        qr[lane + 32] = g_q[base + (size_t)s*TD + lane + 32];
        __syncwarp();
        float lmax = -1e30f;
        for (int k = lane; k < TT; k += 32){
            float dot = 0.f;
            #pragma unroll
            for (int d = 0; d < 64; d++) dot = fmaf(qr[d], Kt[d*200 + k], dot);
            dot *= ATT_SCALE;
            pr[k] = dot;
            lmax = fmaxf(lmax, dot);
        }
        lmax = warpMax(lmax);
        float lsum = 0.f;
        for (int k = lane; k < TT; k += 32){
            float e = expf(pr[k] - lmax);
            pr[k] = e;
            lsum += e;
        }
        lsum = warpSum(lsum);
        float inv = 1.0f / lsum;
        __syncwarp();
        float acc0 = 0.f, acc1 = 0.f;
        for (int k = 0; k < TT; k++){
            float p = pr[k];
            acc0 = fmaf(p, Vs[k*64 + lane],      acc0);
            acc1 = fmaf(p, Vs[k*64 + lane + 32], acc1);
        }
        size_t xi = base + (size_t)s*TD;
        g_x[xi + lane]      += acc0 * inv;
        g_x[xi + lane + 32] += acc1 * inv;
        __syncwarp();
    }
}

// ---------------- tf32 tensor-core GEMM ----------------
// C (epi) A[M,K] @ B[K,N] + bias ; epi: 0 store, 1 gelu, 2 residual +=
// block tile 128x128, k-step 16; 256 threads = 8 warps (4x2), warp tile 32x64
// requires N % 128 == 0, K % 16 == 0
__global__ void __launch_bounds__(256)
tf32gemm_kernel(const float* __restrict__ A, const float* __restrict__ Bm,
                const float* __restrict__ bias, float* __restrict__ C,
                int M, int N, int K, int epi){
    __shared__ float As[128][20];   // [m][k], pad 20 -> conflict-free frag reads
    __shared__ float Bs[16][136];   // [k][n], pad 136 -> conflict-free frag reads

    int tid  = threadIdx.x;
    int lane = tid & 31;
    int warp = tid >> 5;
    int warpM = warp >> 1;          // 0..3
    int warpN = warp & 1;           // 0..1
    int row0 = blockIdx.y * 128;
    int col0 = blockIdx.x * 128;

    float cf[2][8][4];
    #pragma unroll
    for (int mi=0;mi<2;mi++)
        #pragma unroll
        for (int ni=0;ni<8;ni++)
            #pragma unroll
            for (int j=0;j<4;j++) cf[mi][ni][j] = 0.f;

    int ar = tid >> 2;              // A row 0..63 (and +64)
    int ac = (tid & 3) * 4;         // A col 0,4,8,12
    int bk = tid >> 5;              // B k 0..7 (and +8)
    int bc = (tid & 31) * 4;        // B col 0..124

    for (int kk = 0; kk < K; kk += 16){
        #pragma unroll
        for (int half = 0; half < 2; half++){
            int r = ar + half*64;
            int grow = row0 + r;
            float4 v = (grow < M) ? *(const float4*)&A[(size_t)grow*K + kk + ac]
                                  : make_float4(0.f,0.f,0.f,0.f);
            As[r][ac+0] = __uint_as_float(f2tf(v.x));
            As[r][ac+1] = __uint_as_float(f2tf(v.y));
            As[r][ac+2] = __uint_as_float(f2tf(v.z));
            As[r][ac+3] = __uint_as_float(f2tf(v.w));
        }
        #pragma unroll
        for (int half = 0; half < 2; half++){
            int k = bk + half*8;
            float4 v = *(const float4*)&Bm[(size_t)(kk+k)*N + col0 + bc];
            Bs[k][bc+0] = __uint_as_float(f2tf(v.x));
            Bs[k][bc+1] = __uint_as_float(f2tf(v.y));
            Bs[k][bc+2] = __uint_as_float(f2tf(v.z));
            Bs[k][bc+3] = __uint_as_float(f2tf(v.w));
        }
        __syncthreads();

        #pragma unroll
        for (int ks = 0; ks < 16; ks += 8){
            unsigned af[2][4], bf[8][2];
            #pragma unroll
            for (int mi = 0; mi < 2; mi++){
                int m = warpM*32 + mi*16 + (lane >> 2);
                int k = ks + (lane & 3);
                af[mi][0] = __float_as_uint(As[m][k]);
                af[mi][1] = __float_as_uint(As[m+8][k]);
                af[mi][2] = __float_as_uint(As[m][k+4]);
                af[mi][3] = __float_as_uint(As[m+8][k+4]);
            }
            #pragma unroll
            for (int ni = 0; ni < 8; ni++){
                int n = warpN*64 + ni*8 + (lane >> 2);
                bf[ni][0] = __float_as_uint(Bs[ks     + (lane & 3)][n]);
                bf[ni][1] = __float_as_uint(Bs[ks + 4 + (lane & 3)][n]);
            }
            #pragma unroll
            for (int mi = 0; mi < 2; mi++)
                #pragma unroll
                for (int ni = 0; ni < 8; ni++){
                    asm volatile(
                        "mma.sync.aligned.m16n8k8.row.col.f32.tf32.tf32.f32 "
                        "{%0,%1,%2,%3}, {%4,%5,%6,%7}, {%8,%9}, {%0,%1,%2,%3};"
                        : "+f"(cf[mi][ni][0]), "+f"(cf[mi][ni][1]),
                          "+f"(cf[mi][ni][2]), "+f"(cf[mi][ni][3])
                        : "r"(af[mi][0]), "r"(af[mi][1]), "r"(af[mi][2]), "r"(af[mi][3]),
                          "r"(bf[ni][0]), "r"(bf[ni][1]));
                }
        }
        __syncthreads();
    }

    // epilogue
    #pragma unroll
    for (int mi = 0; mi < 2; mi++){
        int rbase = row0 + warpM*32 + mi*16 + (lane >> 2);
        #pragma unroll
        for (int ni = 0; ni < 8; ni++){
            int cbase = col0 + warpN*64 + ni*8 + (lane & 3)*2;
            #pragma unroll
            for (int hh = 0; hh < 2; hh++){
                int r = rbase + hh*8;
                if (r >= M) continue;
                #pragma unroll
                for (int jj = 0; jj < 2; jj++){
                    int c = cbase + jj;
                    float v = cf[mi][ni][hh*2+jj] + bias[c];
                    size_t idx = (size_t)r*N + c;
                    if (epi == 1){
                        C[idx] = 0.5f * v * (1.0f + erff(v * 0.70710678118654752f));
                    } else if (epi == 2){
                        C[idx] += v;
                    } else {
                        C[idx] = v;
                    }
                }
            }
        }
    }
}

// ---------------- classifier head + softmax ----------------
__global__ void classifier_kernel(const float* __restrict__ Wout, const float* __restrict__ bout,
                                  float* __restrict__ out){
    __shared__ float xs[TD];
    __shared__ float lg[OD];
    int b = blockIdx.x;
    int tid = threadIdx.x;
    for (int i = tid; i < TD; i += 256) xs[i] = g_x[((size_t)b*TT)*TD + i];
    __syncthreads();
    for (int n = tid; n < OD; n += 256){
        float s = bout[n];
        for (int d = 0; d < TD; d++) s = fmaf(xs[d], Wout[(size_t)d*OD + n], s);
        lg[n] = s;
    }
    __syncthreads();
    float lm = -1e30f;
    for (int n = tid; n < OD; n += 256) lm = fmaxf(lm, lg[n]);
    lm = blockMax256(lm);
    float ls = 0.f;
    for (int n = tid; n < OD; n += 256){
        float e = expf(lg[n] - lm);
        lg[n] = e;
        ls += e;
    }
    ls = blockSum256(ls);
    float inv = 1.0f / ls;
    for (int n = tid; n < OD; n += 256) out[(size_t)b*OD + n] = lg[n] * inv;
}

// ---------------- host orchestration ----------------
extern "C" void kernel_launch(void* const* d_in, const int* in_sizes, int n_in,
                              void* d_out, int out_size){
    const float* images  = (const float*)d_in[0];
    const float* W_embed = (const float*)d_in[1];
    const float* b_embed = (const float*)d_in[2];
    const float* v_class = (const float*)d_in[3];
    const float* ln1_g   = (const float*)d_in[4];
    const float* ln1_b   = (const float*)d_in[5];
    const float* ln2_g   = (const float*)d_in[6];
    const float* ln2_b   = (const float*)d_in[7];
    const float* Wq      = (const float*)d_in[8];
    const float* bq      = (const float*)d_in[9];
    const float* Wk      = (const float*)d_in[10];
    const float* bk      = (const float*)d_in[11];
    const float* Wv      = (const float*)d_in[12];
    const float* bv      = (const float*)d_in[13];
    const float* Wm1     = (const float*)d_in[14];
    const float* bm1     = (const float*)d_in[15];
    const float* Wm2     = (const float*)d_in[16];
    const float* bm2     = (const float*)d_in[17];
    const float* Wout    = (const float*)d_in[18];
    const float* bout    = (const float*)d_in[19];
    float* out = (float*)d_out;

    float *px, *ph, *pmlp, *ppatch;
    cudaGetSymbolAddress((void**)&px, g_x);
    cudaGetSymbolAddress((void**)&ph, g_h);
    cudaGetSymbolAddress((void**)&pmlp, g_mlp);
    cudaGetSymbolAddress((void**)&ppatch, g_patches);

    const int ATT_SMEM = (64*200 + TT*64 + 8*64 + 8*224) * 4; // 110848 bytes
    cudaFuncSetAttribute(attn_kernel, cudaFuncAttributeMaxDynamicSharedMemorySize, ATT_SMEM);

    // patchify + embed
    patchify_kernel<<<(M_PATCH*TD + 255)/256, 256>>>(images);
    {
        dim3 g(TD/128, (M_PATCH + 127)/128);
        tf32gemm_kernel<<<g, 256>>>(ppatch, W_embed, b_embed, pmlp, M_PATCH, TD, TD, 0);
    }
    assemble_kernel<<<(M_TOK*TD + 255)/256, 256>>>(v_class, pmlp);

    for (int l = 0; l < NB; l++){
        layernorm_kernel<<<M_TOK, 256>>>(px, ph, ln1_g + l*TD, ln1_b + l*TD);
        {
            dim3 g((M_TOK + 63)/64, NH);
            qkv_kernel<<<g, 256>>>(Wq + (size_t)l*NH*64*64, bq + (size_t)l*NH*64,
                                   Wk + (size_t)l*NH*64*64, bk + (size_t)l*NH*64,
                                   Wv + (size_t)l*NH*64*64, bv + (size_t)l*NH*64);
        }
        attn_kernel<<<dim3(NH, BSZ), 256, ATT_SMEM>>>();
        layernorm_kernel<<<M_TOK, 256>>>(px, ph, ln2_g + l*TD, ln2_b + l*TD);
        {
            dim3 g(MD/128, (M_TOK + 127)/128);
            tf32gemm_kernel<<<g, 256>>>(ph, Wm1 + (size_t)l*TD*MD, bm1 + (size_t)l*MD,
                                        pmlp, M_TOK, MD, TD, 1);
        }
        {
            dim3 g(TD/128, (M_TOK + 127)/128);
            tf32gemm_kernel<<<g, 256>>>(pmlp, Wm2 + (size_t)l*MD*TD, bm2 + (size_t)l*TD,
                                        px, M_TOK, TD, MD, 2);
        }
    }

    classifier_kernel<<<BSZ, 256>>>(Wout, bout, out);
}

// round 3
// speedup vs baseline: 2.2963x; 1.2736x over previous
#include <cuda_runtime.h>
#include <cuda_bf16.h>
#include <math.h>

// ---------------- problem constants ----------------
#define BSZ 32
#define TT 197           // tokens
#define TD 768           // token dim
#define NH 12            // heads
#define HD 64            // head dim
#define NB 12            // blocks
#define MD 3072          // mlp dim
#define OD 1000          // out dim
#define NPATCH 196
#define M_TOK (BSZ*TT)   // 6304
#define M_PATCH (BSZ*NPATCH) // 6272
#define ATT_SCALE 0.125f
#define LN_EPS 1e-5f

// ---------------- scratch (device globals, no allocation) ----------------
__device__ float g_x[M_TOK*TD];
__device__ float g_h[M_TOK*TD];
__device__ float g_q[M_TOK*TD];
__device__ float g_k[M_TOK*TD];
__device__ float g_v[M_TOK*TD];
__device__ float g_mlp[(size_t)M_TOK*MD];
__device__ float g_patches[(size_t)M_PATCH*TD];

// ---------------- small reductions ----------------
__device__ __forceinline__ float warpSum(float v){
    #pragma unroll
    for (int o=16;o;o>>=1) v += __shfl_xor_sync(0xffffffffu, v, o);
    return v;
}
__device__ __forceinline__ float warpMax(float v){
    #pragma unroll
    for (int o=16;o;o>>=1) v = fmaxf(v, __shfl_xor_sync(0xffffffffu, v, o));
    return v;
}
__device__ __forceinline__ float blockSum256(float v){
    __shared__ float red[8];
    __shared__ float total;
    int lane = threadIdx.x & 31, w = threadIdx.x >> 5;
    v = warpSum(v);
    if (lane == 0) red[w] = v;
    __syncthreads();
    if (threadIdx.x == 0){ float s=0.f; for(int i=0;i<8;i++) s += red[i]; total = s; }
    __syncthreads();
    float r = total;
    __syncthreads();
    return r;
}
__device__ __forceinline__ float blockMax256(float v){
    __shared__ float red[8];
    __shared__ float total;
    int lane = threadIdx.x & 31, w = threadIdx.x >> 5;
    v = warpMax(v);
    if (lane == 0) red[w] = v;
    __syncthreads();
    if (threadIdx.x == 0){ float s=-1e30f; for(int i=0;i<8;i++) s = fmaxf(s, red[i]); total = s; }
    __syncthreads();
    float r = total;
    __syncthreads();
    return r;
}

// ---------------- tf32 helper ----------------
__device__ __forceinline__ unsigned f2tf(float x){
    unsigned u; asm("cvt.rna.tf32.f32 %0, %1;" : "=r"(u) : "f"(x)); return u;
}

__device__ __forceinline__ unsigned smem_u32(const void* p){
    return (unsigned)__cvta_generic_to_shared(p);
}
__device__ __forceinline__ void cp_async16(unsigned dst, const void* src, int src_bytes){
    asm volatile("cp.async.cg.shared.global [%0], [%1], 16, %2;\n"
                 :: "r"(dst), "l"(src), "r"(src_bytes));
}
__device__ __forceinline__ void cp_commit(){ asm volatile("cp.async.commit_group;\n"); }
template<int N>
__device__ __forceinline__ void cp_wait(){ asm volatile("cp.async.wait_group %0;\n" :: "n"(N)); }

// ---------------- patchify ----------------
__global__ void patchify_kernel(const float* __restrict__ img){
    int idx = blockIdx.x*blockDim.x + threadIdx.x;
    if (idx >= M_PATCH*TD) return;
    int d = idx % TD;
    int mp = idx / TD;
    int b = mp / NPATCH;
    int p = mp % NPATCH;
    int py = p / 14, px = p % 14;
    int c = d >> 8;          // /256
    int r = d & 255;
    int iy = r >> 4, ix = r & 15;
    g_patches[idx] = img[ (((size_t)(b*3 + c)*224) + py*16 + iy)*224 + px*16 + ix ];
}

// ---------------- cls + pos-emb assembly ----------------
__global__ void assemble_kernel(const float* __restrict__ vcls, const float* __restrict__ tokens){
    int idx = blockIdx.x*blockDim.x + threadIdx.x;
    if (idx >= M_TOK*TD) return;
    int d = idx % TD;
    int m = idx / TD;
    int b = m / TT;
    int s = m % TT;
    float val = (s == 0) ? vcls[d] : tokens[(size_t)(b*NPATCH + s - 1)*TD + d];
    float je = (float)(d & ~1);
    float ang = (float)s * exp2f(-je * (13.287712379549449f / 197.0f));
    val += (d & 1) ? cosf(ang) : sinf(ang);
    g_x[idx] = val;
}

// ---------------- layernorm (row per block) ----------------
__global__ void layernorm_kernel(const float* __restrict__ x, float* __restrict__ out,
                                 const float* __restrict__ g, const float* __restrict__ b){
    __shared__ float sdata[TD];
    int row = blockIdx.x;
    const float* xr = x + (size_t)row*TD;
    float local = 0.f;
    for (int i = threadIdx.x; i < TD; i += 256){ float v = xr[i]; sdata[i] = v; local += v; }
    float mean = blockSum256(local) * (1.0f/TD);
    float lv = 0.f;
    for (int i = threadIdx.x; i < TD; i += 256){ float t = sdata[i]-mean; lv += t*t; }
    float var = blockSum256(lv) * (1.0f/TD);
    float rstd = rsqrtf(var + LN_EPS);
    float* orow = out + (size_t)row*TD;
    for (int i = threadIdx.x; i < TD; i += 256)
        orow[i] = (sdata[i]-mean)*rstd*g[i] + b[i];
}

// ---------------- per-head QKV projection ----------------
__global__ void qkv_kernel(const float* __restrict__ Wq, const float* __restrict__ bq,
                           const float* __restrict__ Wk, const float* __restrict__ bk,
                           const float* __restrict__ Wv, const float* __restrict__ bv){
    __shared__ float Hs[64][65];
    __shared__ float Ws[64][64];
    int h = blockIdx.y;
    int m0 = blockIdx.x * 64;
    int tid = threadIdx.x;

    for (int i = tid; i < 64*64; i += 256){
        int r = i >> 6, cc = i & 63;
        int row = m0 + r;
        Hs[r][cc] = (row < M_TOK) ? g_h[(size_t)row*TD + h*64 + cc] : 0.f;
    }
    const float* Wp[3] = {Wq, Wk, Wv};
    const float* bp[3] = {bq, bk, bv};
    float* op[3] = {g_q, g_k, g_v};
    int ty = tid >> 4, tx = tid & 15;

    for (int m = 0; m < 3; m++){
        __syncthreads();
        const float* W = Wp[m] + (size_t)h*64*64;
        for (int i = tid; i < 64*64; i += 256) Ws[i>>6][i&63] = W[i];
        __syncthreads();
        float acc[4][4];
        #pragma unroll
        for (int i=0;i<4;i++)
            #pragma unroll
            for (int j=0;j<4;j++) acc[i][j]=0.f;
        #pragma unroll 8
        for (int kd = 0; kd < 64; kd++){
            float a[4], bb[4];
            #pragma unroll
            for (int i=0;i<4;i++) a[i] = Hs[ty*4+i][kd];
            #pragma unroll
            for (int j=0;j<4;j++) bb[j] = Ws[kd][tx*4+j];
            #pragma unroll
            for (int i=0;i<4;i++)
                #pragma unroll
                for (int j=0;j<4;j++) acc[i][j] = fmaf(a[i], bb[j], acc[i][j]);
        }
        #pragma unroll
        for (int i=0;i<4;i++){
            int row = m0 + ty*4 + i;
            if (row >= M_TOK) continue;
            #pragma unroll
            for (int j=0;j<4;j++){
                int e = tx*4 + j;
                op[m][(size_t)row*TD + h*64 + e] = acc[i][j] + bp[m][h*64 + e];
            }
        }
    }
}

// ---------------- fused attention (per (b,h)), residual add into x ----------------
__global__ void attn_kernel(){
    extern __shared__ float sm[];
    float* Kt = sm;                 // [64][200]
    float* Vs = Kt + 64*200;        // [197][64]
    float* q8 = Vs + TT*64;         // [8][64]
    float* p8 = q8 + 8*64;          // [8][224]

    int h = blockIdx.x, b = blockIdx.y;
    int tid = threadIdx.x;
    size_t base = ((size_t)b*TT)*TD + h*64;

    for (int i = tid; i < TT*64; i += 256){
        int k = i >> 6, d = i & 63;
        float kv = g_k[base + (size_t)k*TD + d];
        Kt[d*200 + k] = kv;
        Vs[i] = g_v[base + (size_t)k*TD + d];
    }
    __syncthreads();

    int w = tid >> 5, lane = tid & 31;
    float* qr = q8 + w*64;
    float* pr = p8 + w*224;

    for (int s = w; s < TT; s += 8){
        qr[lane]      = g_q[base + (size_t)s*TD + lane];
        qr[lane + 32] = g_q[base + (size_t)s*TD + lane + 32];
        __syncwarp();
        float lmax = -1e30f;
        for (int k = lane; k < TT; k += 32){
            float dot = 0.f;
            #pragma unroll
            for (int d = 0; d < 64; d++) dot = fmaf(qr[d], Kt[d*200 + k], dot);
            dot *= ATT_SCALE;
            pr[k] = dot;
            lmax = fmaxf(lmax, dot);
        }
        lmax = warpMax(lmax);
        float lsum = 0.f;
        for (int k = lane; k < TT; k += 32){
            float e = expf(pr[k] - lmax);
            pr[k] = e;
            lsum += e;
        }
        lsum = warpSum(lsum);
        float inv = 1.0f / lsum;
        __syncwarp();
        float acc0 = 0.f, acc1 = 0.f;
        for (int k = 0; k < TT; k++){
            float p = pr[k];
            acc0 = fmaf(p, Vs[k*64 + lane],      acc0);
            acc1 = fmaf(p, Vs[k*64 + lane + 32], acc1);
        }
        size_t xi = base + (size_t)s*TD;
        g_x[xi + lane]      += acc0 * inv;
        g_x[xi + lane + 32] += acc1 * inv;
        __syncwarp();
    }
}

// ---------------- tf32 tensor-core GEMM with cp.async double buffering ----------------
// C (epi) A[M,K] @ B[K,N] + bias ; epi: 0 store, 1 gelu, 2 residual +=
// block tile 128x128, k-step 16; 256 threads = 8 warps (4x2), warp tile 32x64
// requires N % 128 == 0, K % 16 == 0
__global__ void __launch_bounds__(256)
tf32gemm_kernel(const float* __restrict__ A, const float* __restrict__ Bm,
                const float* __restrict__ bias, float* __restrict__ C,
                int M, int N, int K, int epi){
    __shared__ float As[2][128][20];   // [buf][m][k], raw fp32
    __shared__ float Bs[2][16][136];   // [buf][k][n], raw fp32

    int tid  = threadIdx.x;
    int lane = tid & 31;
    int warp = tid >> 5;
    int warpM = warp >> 1;          // 0..3
    int warpN = warp & 1;           // 0..1
    int row0 = blockIdx.y * 128;
    int col0 = blockIdx.x * 128;

    float cf[2][8][4];
    #pragma unroll
    for (int mi=0;mi<2;mi++)
        #pragma unroll
        for (int ni=0;ni<8;ni++)
            #pragma unroll
            for (int j=0;j<4;j++) cf[mi][ni][j] = 0.f;

    int ar = tid >> 2;              // A row 0..63 (and +64)
    int ac = (tid & 3) * 4;         // A col 0,4,8,12
    int bk = tid >> 5;              // B k 0..7 (and +8)
    int bc = (tid & 31) * 4;        // B col 0..124

    int KT = K >> 4;

    // prologue: load tile 0 into buf 0
    {
        #pragma unroll
        for (int half = 0; half < 2; half++){
            int r = ar + half*64;
            int grow = row0 + r;
            cp_async16(smem_u32(&As[0][r][ac]), &A[(size_t)grow*K + ac],
                       (grow < M) ? 16 : 0);
        }
        #pragma unroll
        for (int half = 0; half < 2; half++){
            int k = bk + half*8;
            cp_async16(smem_u32(&Bs[0][k][bc]), &Bm[(size_t)k*N + col0 + bc], 16);
        }
        cp_commit();
    }

    for (int kt = 0; kt < KT; kt++){
        int buf = kt & 1;
        // prefetch next tile into other buffer
        if (kt + 1 < KT){
            int nb = buf ^ 1;
            int kk = (kt + 1) << 4;
            #pragma unroll
            for (int half = 0; half < 2; half++){
                int r = ar + half*64;
                int grow = row0 + r;
                cp_async16(smem_u32(&As[nb][r][ac]), &A[(size_t)grow*K + kk + ac],
                           (grow < M) ? 16 : 0);
            }
            #pragma unroll
            for (int half = 0; half < 2; half++){
                int k = bk + half*8;
                cp_async16(smem_u32(&Bs[nb][k][bc]), &Bm[(size_t)(kk+k)*N + col0 + bc], 16);
            }
            cp_commit();
            cp_wait<1>();
        } else {
            cp_wait<0>();
        }
        __syncthreads();

        #pragma unroll
        for (int ks = 0; ks < 16; ks += 8){
            unsigned af[2][4], bf[8][2];
            #pragma unroll
            for (int mi = 0; mi < 2; mi++){
                int m = warpM*32 + mi*16 + (lane >> 2);
                int k = ks + (lane & 3);
                af[mi][0] = f2tf(As[buf][m][k]);
                af[mi][1] = f2tf(As[buf][m+8][k]);
                af[mi][2] = f2tf(As[buf][m][k+4]);
                af[mi][3] = f2tf(As[buf][m+8][k+4]);
            }
            #pragma unroll
            for (int ni = 0; ni < 8; ni++){
                int n = warpN*64 + ni*8 + (lane >> 2);
                bf[ni][0] = f2tf(Bs[buf][ks     + (lane & 3)][n]);
                bf[ni][1] = f2tf(Bs[buf][ks + 4 + (lane & 3)][n]);
            }
            #pragma unroll
            for (int mi = 0; mi < 2; mi++)
                #pragma unroll
                for (int ni = 0; ni < 8; ni++){
                    asm volatile(
                        "mma.sync.aligned.m16n8k8.row.col.f32.tf32.tf32.f32 "
                        "{%0,%1,%2,%3}, {%4,%5,%6,%7}, {%8,%9}, {%0,%1,%2,%3};"
                        : "+f"(cf[mi][ni][0]), "+f"(cf[mi][ni][1]),
                          "+f"(cf[mi][ni][2]), "+f"(cf[mi][ni][3])
                        : "r"(af[mi][0]), "r"(af[mi][1]), "r"(af[mi][2]), "r"(af[mi][3]),
                          "r"(bf[ni][0]), "r"(bf[ni][1]));
                }
        }
        __syncthreads();   // protect buf from being overwritten by next prefetch
    }

    // epilogue
    #pragma unroll
    for (int mi = 0; mi < 2; mi++){
        int rbase = row0 + warpM*32 + mi*16 + (lane >> 2);
        #pragma unroll
        for (int ni = 0; ni < 8; ni++){
            int cbase = col0 + warpN*64 + ni*8 + (lane & 3)*2;
            #pragma unroll
            for (int hh = 0; hh < 2; hh++){
                int r = rbase + hh*8;
                if (r >= M) continue;
                #pragma unroll
                for (int jj = 0; jj < 2; jj++){
                    int c = cbase + jj;
                    float v = cf[mi][ni][hh*2+jj] + bias[c];
                    size_t idx = (size_t)r*N + c;
                    if (epi == 1){
                        C[idx] = 0.5f * v * (1.0f + erff(v * 0.70710678118654752f));
                    } else if (epi == 2){
                        C[idx] += v;
                    } else {
                        C[idx] = v;
                    }
                }
            }
        }
    }
}

// ---------------- classifier head + softmax ----------------
__global__ void classifier_kernel(const float* __restrict__ Wout, const float* __restrict__ bout,
                                  float* __restrict__ out){
    __shared__ float xs[TD];
    __shared__ float lg[OD];
    int b = blockIdx.x;
    int tid = threadIdx.x;
    for (int i = tid; i < TD; i += 256) xs[i] = g_x[((size_t)b*TT)*TD + i];
    __syncthreads();
    for (int n = tid; n < OD; n += 256){
        float s = bout[n];
        for (int d = 0; d < TD; d++) s = fmaf(xs[d], Wout[(size_t)d*OD + n], s);
        lg[n] = s;
    }
    __syncthreads();
    float lm = -1e30f;
    for (int n = tid; n < OD; n += 256) lm = fmaxf(lm, lg[n]);
    lm = blockMax256(lm);
    float ls = 0.f;
    for (int n = tid; n < OD; n += 256){
        float e = expf(lg[n] - lm);
        lg[n] = e;
        ls += e;
    }
    ls = blockSum256(ls);
    float inv = 1.0f / ls;
    for (int n = tid; n < OD; n += 256) out[(size_t)b*OD + n] = lg[n] * inv;
}

// ---------------- host orchestration ----------------
extern "C" void kernel_launch(void* const* d_in, const int* in_sizes, int n_in,
                              void* d_out, int out_size){
    const float* images  = (const float*)d_in[0];
    const float* W_embed = (const float*)d_in[1];
    const float* b_embed = (const float*)d_in[2];
    const float* v_class = (const float*)d_in[3];
    const float* ln1_g   = (const float*)d_in[4];
    const float* ln1_b   = (const float*)d_in[5];
    const float* ln2_g   = (const float*)d_in[6];
    const float* ln2_b   = (const float*)d_in[7];
    const float* Wq      = (const float*)d_in[8];
    const float* bq      = (const float*)d_in[9];
    const float* Wk      = (const float*)d_in[10];
    const float* bk      = (const float*)d_in[11];
    const float* Wv      = (const float*)d_in[12];
    const float* bv      = (const float*)d_in[13];
    const float* Wm1     = (const float*)d_in[14];
    const float* bm1     = (const float*)d_in[15];
    const float* Wm2     = (const float*)d_in[16];
    const float* bm2     = (const float*)d_in[17];
    const float* Wout    = (const float*)d_in[18];
    const float* bout    = (const float*)d_in[19];
    float* out = (float*)d_out;

    float *px, *ph, *pmlp, *ppatch;
    cudaGetSymbolAddress((void**)&px, g_x);
    cudaGetSymbolAddress((void**)&ph, g_h);
    cudaGetSymbolAddress((void**)&pmlp, g_mlp);
    cudaGetSymbolAddress((void**)&ppatch, g_patches);

    const int ATT_SMEM = (64*200 + TT*64 + 8*64 + 8*224) * 4; // 110848 bytes
    cudaFuncSetAttribute(attn_kernel, cudaFuncAttributeMaxDynamicSharedMemorySize, ATT_SMEM);

    // patchify + embed
    patchify_kernel<<<(M_PATCH*TD + 255)/256, 256>>>(images);
    {
        dim3 g(TD/128, (M_PATCH + 127)/128);
        tf32gemm_kernel<<<g, 256>>>(ppatch, W_embed, b_embed, pmlp, M_PATCH, TD, TD, 0);
    }
    assemble_kernel<<<(M_TOK*TD + 255)/256, 256>>>(v_class, pmlp);

    for (int l = 0; l < NB; l++){
        layernorm_kernel<<<M_TOK, 256>>>(px, ph, ln1_g + l*TD, ln1_b + l*TD);
        {
            dim3 g((M_TOK + 63)/64, NH);
            qkv_kernel<<<g, 256>>>(Wq + (size_t)l*NH*64*64, bq + (size_t)l*NH*64,
                                   Wk + (size_t)l*NH*64*64, bk + (size_t)l*NH*64,
                                   Wv + (size_t)l*NH*64*64, bv + (size_t)l*NH*64);
        }
        attn_kernel<<<dim3(NH, BSZ), 256, ATT_SMEM>>>();
        layernorm_kernel<<<M_TOK, 256>>>(px, ph, ln2_g + l*TD, ln2_b + l*TD);
        {
            dim3 g(MD/128, (M_TOK + 127)/128);
            tf32gemm_kernel<<<g, 256>>>(ph, Wm1 + (size_t)l*TD*MD, bm1 + (size_t)l*MD,
                                        pmlp, M_TOK, MD, TD, 1);
        }
        {
            dim3 g(TD/128, (M_TOK + 127)/128);
            tf32gemm_kernel<<<g, 256>>>(pmlp, Wm2 + (size_t)l*MD*TD, bm2 + (size_t)l*TD,
                                        px, M_TOK, TD, MD, 2);
        }
    }

    classifier_kernel<<<BSZ, 256>>>(Wout, bout, out);
}